// round 14
// baseline (speedup 1.0000x reference)
#include <cuda_runtime.h>
#include <cuda_bf16.h>
#include <math.h>

#define NN 50000
#define DD 128
#define EE 800000
#define LL 3

// ---------------- scratch (device globals: no allocation allowed) ----------------
__device__ float g_zin[NN * DD];
__device__ float g_z1[NN * 2 * DD];
__device__ float g_hA[NN * DD];
__device__ float g_hB[NN * DD];
__device__ int   g_cnt[NN];
__device__ int   g_off[NN + 1];
__device__ int   g_cursor[NN];
__device__ int   g_esrc[EE];
__device__ int   g_boff[256];
__device__ float g_sc1[LL * 256];
__device__ float g_sh1[LL * 256];
__device__ float g_sc2[2 * 128];
__device__ float g_sh2[2 * 128];
// split-bf16 weight images in the GEMM's per-thread B-load order:
__device__ uint4 g_w1img[6 * 4096];
__device__ uint4 g_w2img[3 * 8192];

// ---------------- helpers ----------------
__device__ __forceinline__ void split8(const float* f, uint4* h, uint4* l) {
    union { uint4 u; __nv_bfloat162 p[4]; } H, Lo;
#pragma unroll
    for (int j = 0; j < 4; j++) {
        float x0 = f[2 * j], x1 = f[2 * j + 1];
        __nv_bfloat16 h0 = __float2bfloat16(x0), h1 = __float2bfloat16(x1);
        H.p[j] = __nv_bfloat162(h0, h1);
        Lo.p[j] = __nv_bfloat162(__float2bfloat16(x0 - __bfloat162float(h0)),
                                 __float2bfloat16(x1 - __bfloat162float(h1)));
    }
    *h = H.u; *l = Lo.u;
}

// ---------------- merged setup: weight images + BN fold + cnt zero ----------------
__global__ void k_setup(const float* __restrict__ W1, const float* __restrict__ W2,
                        const float* __restrict__ b1, const float* __restrict__ g1,
                        const float* __restrict__ be1, const float* __restrict__ m1,
                        const float* __restrict__ v1, const float* __restrict__ b2,
                        const float* __restrict__ go, const float* __restrict__ bo,
                        const float* __restrict__ mo, const float* __restrict__ vo) {
    int b = blockIdx.x;
    int tid = threadIdx.x;
    if (b < 192) {
        int t = b * 256 + tid;  // 49152 total
        int half = t / 24576;
        int r = t % 24576;
        float f[8];
        uint4 h, l4;
        if (half == 0) {
            int lny = r >> 12;
            int rem = r & 4095;
            int kt = rem >> 9;
            int hl = (rem >> 8) & 1;
            int c = rem & 255;
            int krow = c >> 4, chunk = c & 15;
            int l = lny >> 1, ny = lny & 1;
            int k = kt * 16 + krow;
            int n = ny * 128 + chunk * 8;
#pragma unroll
            for (int j = 0; j < 8; j++)
                f[j] = W1[(size_t)l * 128 * 256 + (size_t)k * 256 + n + j];
            split8(f, &h, &l4);
            g_w1img[r] = hl ? l4 : h;
        } else {
            int l = r >> 13;
            int rem = r & 8191;
            int kt = rem >> 9;
            int hl = (rem >> 8) & 1;
            int c = rem & 255;
            int krow = c >> 4, chunk = c & 15;
            int k = kt * 16 + krow;
            int n = chunk * 8;
#pragma unroll
            for (int j = 0; j < 8; j++)
                f[j] = W2[(size_t)l * 256 * 128 + (size_t)k * 128 + n + j];
            split8(f, &h, &l4);
            g_w2img[r] = hl ? l4 : h;
        }
    } else if (b < 195) {
        int i = (b - 192) * 256 + tid;
        if (i < LL * 256) {
            float sc = g1[i] * rsqrtf(v1[i] + 1e-5f);
            g_sc1[i] = sc;
            g_sh1[i] = be1[i] - m1[i] * sc + b1[i] * sc;
        }
        if (i < 2 * 128) {
            float sc = go[i] * rsqrtf(vo[i] + 1e-5f);
            g_sc2[i] = sc;
            g_sh2[i] = bo[i] - mo[i] * sc + b2[i] * sc;
        }
    } else {
        int i = (b - 195) * 256 + tid;
        if (i < NN) g_cnt[i] = 0;
    }
}

// ---------------- CSR build ----------------
__global__ void k_hist(const int* __restrict__ dstp) {
    int e2 = blockIdx.x * blockDim.x + threadIdx.x;
    if (e2 * 2 < EE) {
        int2 d = *(const int2*)(dstp + e2 * 2);
        atomicAdd(&g_cnt[d.x], 1);
        atomicAdd(&g_cnt[d.y], 1);
    }
}
__global__ void k_bsum() {
    __shared__ int sh[8];
    int i = blockIdx.x * 256 + threadIdx.x;
    int lane = threadIdx.x & 31, warp = threadIdx.x >> 5;
    int v = (i < NN) ? g_cnt[i] : 0;
#pragma unroll
    for (int o = 16; o; o >>= 1) v += __shfl_xor_sync(0xffffffffu, v, o);
    if (lane == 0) sh[warp] = v;
    __syncthreads();
    if (threadIdx.x == 0) {
        int s = 0;
#pragma unroll
        for (int w = 0; w < 8; w++) s += sh[w];
        g_boff[blockIdx.x] = s;
    }
}
__global__ void k_bscan() {
    __shared__ int s[256];
    int t = threadIdx.x;
    s[t] = (t < 196) ? g_boff[t] : 0;
    __syncthreads();
    for (int off = 1; off < 256; off <<= 1) {
        int v = (t >= off) ? s[t - off] : 0;
        __syncthreads();
        s[t] += v;
        __syncthreads();
    }
    g_boff[t] = (t > 0) ? s[t - 1] : 0;
}
__global__ void k_apply() {
    __shared__ int s[256];
    int b = blockIdx.x, t = threadIdx.x;
    int i = b * 256 + t;
    int c = (i < NN) ? g_cnt[i] : 0;
    s[t] = c;
    __syncthreads();
    for (int off = 1; off < 256; off <<= 1) {
        int v = (t >= off) ? s[t - off] : 0;
        __syncthreads();
        s[t] += v;
        __syncthreads();
    }
    if (i < NN) {
        int o = g_boff[b] + s[t] - c;
        g_off[i] = o;
        g_cursor[i] = o;
    }
    if (b == 0 && t == 0) g_off[NN] = EE;
}
__global__ void k_fill(const int* __restrict__ srcp, const int* __restrict__ dstp) {
    int e2 = blockIdx.x * blockDim.x + threadIdx.x;
    if (e2 * 2 < EE) {
        int2 d = *(const int2*)(dstp + e2 * 2);
        int2 s = *(const int2*)(srcp + e2 * 2);
        int p0 = atomicAdd(&g_cursor[d.x], 1);
        g_esrc[p0] = s.x;
        int p1 = atomicAdd(&g_cursor[d.y], 1);
        g_esrc[p1] = s.y;
    }
}

// ---------------- aggregation: zin = (1+eps)*h + segment_sum(h[src] by dst) ----------------
__global__ void k_agg(const float* __restrict__ hin, const float* __restrict__ epsp, int l) {
    int warp = (blockIdx.x * blockDim.x + threadIdx.x) >> 5;
    int lane = threadIdx.x & 31;
    if (warp >= NN) return;
    int beg = g_off[warp];
    int end = g_off[warp + 1];
    float4 acc = make_float4(0.f, 0.f, 0.f, 0.f);
    for (int j = beg; j < end; j += 32) {
        int myidx = j + lane;
        int s = (myidx < end) ? g_esrc[myidx] : 0;
        int cnt = min(32, end - j);
        int t = 0;
        for (; t + 4 <= cnt; t += 4) {
            int s0 = __shfl_sync(0xffffffffu, s, t);
            int s1 = __shfl_sync(0xffffffffu, s, t + 1);
            int s2 = __shfl_sync(0xffffffffu, s, t + 2);
            int s3 = __shfl_sync(0xffffffffu, s, t + 3);
            float4 v0 = *(const float4*)(hin + (size_t)s0 * DD + lane * 4);
            float4 v1 = *(const float4*)(hin + (size_t)s1 * DD + lane * 4);
            float4 v2 = *(const float4*)(hin + (size_t)s2 * DD + lane * 4);
            float4 v3 = *(const float4*)(hin + (size_t)s3 * DD + lane * 4);
            acc.x += v0.x + v1.x + v2.x + v3.x;
            acc.y += v0.y + v1.y + v2.y + v3.y;
            acc.z += v0.z + v1.z + v2.z + v3.z;
            acc.w += v0.w + v1.w + v2.w + v3.w;
        }
        for (; t < cnt; t++) {
            int sj = __shfl_sync(0xffffffffu, s, t);
            float4 v = *(const float4*)(hin + (size_t)sj * DD + lane * 4);
            acc.x += v.x; acc.y += v.y; acc.z += v.z; acc.w += v.w;
        }
    }
    float ev = 1.0f + epsp[l];
    float4 hv = *(const float4*)(hin + (size_t)warp * DD + lane * 4);
    acc.x += ev * hv.x; acc.y += ev * hv.y; acc.z += ev * hv.z; acc.w += ev * hv.w;
    *(float4*)(g_zin + (size_t)warp * DD + lane * 4) = acc;
}

// ---------------- split-bf16 tensor-core GEMM, double-buffered, fused epilogue ----------------
// outmode: 1 = relu(acc*scale+shift) ; 2 = acc+shift then log_softmax over full row (BN==Nn==128)
#define BM 128
#define BN 128
#define BK 16
#define ASTR 24
#define BSTR 136

__device__ __forceinline__ void ldsm4(unsigned r[4], const __nv_bfloat16* p) {
    unsigned addr = (unsigned)__cvta_generic_to_shared(p);
    asm volatile("ldmatrix.sync.aligned.m8n8.x4.shared.b16 {%0,%1,%2,%3}, [%4];"
                 : "=r"(r[0]), "=r"(r[1]), "=r"(r[2]), "=r"(r[3]) : "r"(addr));
}
__device__ __forceinline__ void ldsm4t(unsigned r[4], const __nv_bfloat16* p) {
    unsigned addr = (unsigned)__cvta_generic_to_shared(p);
    asm volatile("ldmatrix.sync.aligned.m8n8.x4.trans.shared.b16 {%0,%1,%2,%3}, [%4];"
                 : "=r"(r[0]), "=r"(r[1]), "=r"(r[2]), "=r"(r[3]) : "r"(addr));
}
__device__ __forceinline__ void mma16816(float c[4], const unsigned a[4], unsigned b0, unsigned b1) {
    asm volatile("mma.sync.aligned.m16n8k16.row.col.f32.bf16.bf16.f32 "
                 "{%0,%1,%2,%3},{%4,%5,%6,%7},{%8,%9},{%0,%1,%2,%3};"
                 : "+f"(c[0]), "+f"(c[1]), "+f"(c[2]), "+f"(c[3])
                 : "r"(a[0]), "r"(a[1]), "r"(a[2]), "r"(a[3]), "r"(b0), "r"(b1));
}

__global__ __launch_bounds__(256, 2) void k_gemm(
    const float* __restrict__ A, const uint4* __restrict__ Bimg, float* __restrict__ C,
    int M, int Nn, int K,
    const float* __restrict__ scale, const float* __restrict__ shift, int outmode) {
    __shared__ __align__(16) __nv_bfloat16 Ah[2][BM * ASTR];
    __shared__ __align__(16) __nv_bfloat16 Al[2][BM * ASTR];
    __shared__ __align__(16) __nv_bfloat16 Bh[2][BK * BSTR];
    __shared__ __align__(16) __nv_bfloat16 Bl[2][BK * BSTR];
    __shared__ float rred[BM][2];   // row reduction scratch for outmode 2

    int tid = threadIdx.x;
    int lane = tid & 31, warp = tid >> 5;
    int wm = (warp >> 1) * 32;
    int wn = (warp & 1) * 64;
    int m0 = blockIdx.x * BM, n0 = blockIdx.y * BN;
    Bimg += (size_t)blockIdx.y * 4096;

    float acc[2][8][4];
#pragma unroll
    for (int i = 0; i < 2; i++)
#pragma unroll
        for (int j = 0; j < 8; j++)
#pragma unroll
            for (int q = 0; q < 4; q++) acc[i][j][q] = 0.f;

    float4 ar[2];
    uint4 brh, brl;
    const int a_row0 = tid >> 2, a_c4 = tid & 3;
    const int a_row1 = (tid + 256) >> 2;
    const int b_krow = tid >> 4, b_chunk = tid & 15;

#define LDG_TILE(kt)                                                                     \
    {                                                                                    \
        int gr0 = m0 + a_row0, gr1 = m0 + a_row1;                                        \
        int k0 = (kt) * BK;                                                              \
        ar[0] = (gr0 < M) ? *(const float4*)(A + (size_t)gr0 * K + k0 + a_c4 * 4)        \
                          : make_float4(0.f, 0.f, 0.f, 0.f);                             \
        ar[1] = (gr1 < M) ? *(const float4*)(A + (size_t)gr1 * K + k0 + a_c4 * 4)        \
                          : make_float4(0.f, 0.f, 0.f, 0.f);                             \
        brh = Bimg[(kt) * 512 + tid];                                                    \
        brl = Bimg[(kt) * 512 + 256 + tid];                                              \
    }

#define STS_TILE(st)                                                                     \
    {                                                                                    \
        _Pragma("unroll") for (int p = 0; p < 2; p++) {                                  \
            int arow = p ? a_row1 : a_row0;                                              \
            const float* v = (const float*)&ar[p];                                       \
            _Pragma("unroll") for (int j = 0; j < 2; j++) {                              \
                __nv_bfloat16 h0 = __float2bfloat16(v[2 * j]);                           \
                __nv_bfloat16 h1 = __float2bfloat16(v[2 * j + 1]);                       \
                __nv_bfloat16 l0 = __float2bfloat16(v[2 * j] - __bfloat162float(h0));    \
                __nv_bfloat16 l1 = __float2bfloat16(v[2 * j + 1] - __bfloat162float(h1));\
                *(__nv_bfloat162*)&Ah[st][arow * ASTR + a_c4 * 4 + 2 * j] =              \
                    __nv_bfloat162(h0, h1);                                              \
                *(__nv_bfloat162*)&Al[st][arow * ASTR + a_c4 * 4 + 2 * j] =              \
                    __nv_bfloat162(l0, l1);                                              \
            }                                                                            \
        }                                                                                \
        *(uint4*)&Bh[st][b_krow * BSTR + b_chunk * 8] = brh;                             \
        *(uint4*)&Bl[st][b_krow * BSTR + b_chunk * 8] = brl;                             \
    }

    const int a_lrow = wm + (lane & 15);
    const int a_lkof = (lane >> 4) * 8;
    const int b_lk = (lane & 7) + ((lane >> 3) & 1) * 8;
    const int b_lnof = ((lane >> 4) & 1) * 8;

#define LDB(BS, bfr)                                                                     \
    {                                                                                    \
        _Pragma("unroll") for (int ntp = 0; ntp < 4; ntp++)                              \
            ldsm4t(bfr[ntp], &BS[b_lk * BSTR + wn + ntp * 16 + b_lnof]);                 \
    }
#define PASSF(AS, bfr)                                                                   \
    {                                                                                    \
        unsigned afr[2][4];                                                              \
        _Pragma("unroll") for (int mt = 0; mt < 2; mt++)                                 \
            ldsm4(afr[mt], &AS[(a_lrow + mt * 16) * ASTR + a_lkof]);                     \
        _Pragma("unroll") for (int mt = 0; mt < 2; mt++)                                 \
            _Pragma("unroll") for (int ntp = 0; ntp < 4; ntp++) {                        \
                mma16816(acc[mt][2 * ntp], afr[mt], bfr[ntp][0], bfr[ntp][1]);           \
                mma16816(acc[mt][2 * ntp + 1], afr[mt], bfr[ntp][2], bfr[ntp][3]);       \
            }                                                                            \
    }

    LDG_TILE(0);
    STS_TILE(0);
    __syncthreads();
    int nIter = K / BK;
    for (int t = 0; t < nIter; t++) {
        int cur = t & 1, nxt = cur ^ 1;
        bool have = (t + 1 < nIter);
        if (have) LDG_TILE(t + 1);
        {
            unsigned bfr[4][4];
            LDB(Bh[cur], bfr);
            PASSF(Ah[cur], bfr);
            PASSF(Al[cur], bfr);
            LDB(Bl[cur], bfr);
            PASSF(Ah[cur], bfr);
        }
        if (have) STS_TILE(nxt);
        __syncthreads();
    }

    int grp = lane >> 2, tig = lane & 3;
    if (outmode == 1) {
#pragma unroll
        for (int mt = 0; mt < 2; mt++) {
#pragma unroll
            for (int nt = 0; nt < 8; nt++) {
                int col = n0 + wn + nt * 8 + tig * 2;
                float2 sc = *(const float2*)(scale + col);
                float2 sh = *(const float2*)(shift + col);
                int row0 = m0 + wm + mt * 16 + grp;
                int row1 = row0 + 8;
                float* c = acc[mt][nt];
                float2 o0, o1;
                o0.x = fmaxf(c[0] * sc.x + sh.x, 0.f);
                o0.y = fmaxf(c[1] * sc.y + sh.y, 0.f);
                o1.x = fmaxf(c[2] * sc.x + sh.x, 0.f);
                o1.y = fmaxf(c[3] * sc.y + sh.y, 0.f);
                if (row0 < M) *(float2*)(C + (size_t)row0 * Nn + col) = o0;
                if (row1 < M) *(float2*)(C + (size_t)row1 * Nn + col) = o1;
            }
        }
    } else {
        // outmode 2: out = acc + shift, then log_softmax over the full row (BN == Nn)
        float v[2][2][16];  // [mt][rowhalf][8 nt * 2 cols]
#pragma unroll
        for (int mt = 0; mt < 2; mt++)
#pragma unroll
            for (int nt = 0; nt < 8; nt++) {
                int col = wn + nt * 8 + tig * 2;
                float2 sh = *(const float2*)(shift + col);
                float* c = acc[mt][nt];
                v[mt][0][2 * nt] = c[0] + sh.x;
                v[mt][0][2 * nt + 1] = c[1] + sh.y;
                v[mt][1][2 * nt] = c[2] + sh.x;
                v[mt][1][2 * nt + 1] = c[3] + sh.y;
            }
        // phase A: row max
#pragma unroll
        for (int mt = 0; mt < 2; mt++)
#pragma unroll
            for (int rh = 0; rh < 2; rh++) {
                float mx = v[mt][rh][0];
#pragma unroll
                for (int q = 1; q < 16; q++) mx = fmaxf(mx, v[mt][rh][q]);
                mx = fmaxf(mx, __shfl_xor_sync(0xffffffffu, mx, 1));
                mx = fmaxf(mx, __shfl_xor_sync(0xffffffffu, mx, 2));
                if (tig == 0) rred[wm + mt * 16 + rh * 8 + grp][warp & 1] = mx;
            }
        __syncthreads();
        float rmax[2][2];
#pragma unroll
        for (int mt = 0; mt < 2; mt++)
#pragma unroll
            for (int rh = 0; rh < 2; rh++) {
                int rl = wm + mt * 16 + rh * 8 + grp;
                rmax[mt][rh] = fmaxf(rred[rl][0], rred[rl][1]);
            }
        __syncthreads();
        // phase B: row sum of exp
#pragma unroll
        for (int mt = 0; mt < 2; mt++)
#pragma unroll
            for (int rh = 0; rh < 2; rh++) {
                float s = 0.f;
#pragma unroll
                for (int q = 0; q < 16; q++) s += __expf(v[mt][rh][q] - rmax[mt][rh]);
                s += __shfl_xor_sync(0xffffffffu, s, 1);
                s += __shfl_xor_sync(0xffffffffu, s, 2);
                if (tig == 0) rred[wm + mt * 16 + rh * 8 + grp][warp & 1] = s;
            }
        __syncthreads();
        // phase C: write normalized
#pragma unroll
        for (int mt = 0; mt < 2; mt++)
#pragma unroll
            for (int rh = 0; rh < 2; rh++) {
                int rl = wm + mt * 16 + rh * 8 + grp;
                int row = m0 + rl;
                if (row >= M) continue;
                float lse = rmax[mt][rh] + __logf(rred[rl][0] + rred[rl][1]);
#pragma unroll
                for (int nt = 0; nt < 8; nt++) {
                    int col = wn + nt * 8 + tig * 2;
                    float2 o;
                    o.x = v[mt][rh][2 * nt] - lse;
                    o.y = v[mt][rh][2 * nt + 1] - lse;
                    *(float2*)(C + (size_t)row * Nn + col) = o;
                }
            }
    }
#undef LDG_TILE
#undef STS_TILE
#undef LDB
#undef PASSF
}

// ---------------- launch ----------------
extern "C" void kernel_launch(void* const* d_in, const int* in_sizes, int n_in,
                              void* d_out, int out_size) {
    const float* x   = (const float*)d_in[0];
    const int*   ei  = (const int*)d_in[1];
    const float* W1  = (const float*)d_in[2];
    const float* b1  = (const float*)d_in[3];
    const float* g1  = (const float*)d_in[4];
    const float* be1 = (const float*)d_in[5];
    const float* m1  = (const float*)d_in[6];
    const float* v1  = (const float*)d_in[7];
    const float* W2  = (const float*)d_in[8];
    const float* b2  = (const float*)d_in[9];
    const float* eps = (const float*)d_in[10];
    const float* go  = (const float*)d_in[11];
    const float* bo  = (const float*)d_in[12];
    const float* mo  = (const float*)d_in[13];
    const float* vo  = (const float*)d_in[14];
    const int* srcp = ei;
    const int* dstp = ei + EE;

    float *zin, *z1p, *hA, *hB, *sc1, *sh1, *sc2, *sh2;
    uint4 *w1i, *w2i;
    cudaGetSymbolAddress((void**)&zin, g_zin);
    cudaGetSymbolAddress((void**)&z1p, g_z1);
    cudaGetSymbolAddress((void**)&hA, g_hA);
    cudaGetSymbolAddress((void**)&hB, g_hB);
    cudaGetSymbolAddress((void**)&sc1, g_sc1);
    cudaGetSymbolAddress((void**)&sh1, g_sh1);
    cudaGetSymbolAddress((void**)&sc2, g_sc2);
    cudaGetSymbolAddress((void**)&sh2, g_sh2);
    cudaGetSymbolAddress((void**)&w1i, g_w1img);
    cudaGetSymbolAddress((void**)&w2i, g_w2img);

    k_setup<<<391, 256>>>(W1, W2, b1, g1, be1, m1, v1, b2, go, bo, mo, vo);
    k_hist<<<(EE / 2 + 255) / 256, 256>>>(dstp);
    const int SB = (NN + 255) / 256;  // 196
    k_bsum<<<SB, 256>>>();
    k_bscan<<<1, 256>>>();
    k_apply<<<SB, 256>>>();
    k_fill<<<(EE / 2 + 255) / 256, 256>>>(srcp, dstp);

    const int MT = (NN + BM - 1) / BM;  // 391
    for (int l = 0; l < LL; l++) {
        const float* hin = (l == 0) ? x : ((l == 1) ? hA : hB);
        k_agg<<<(NN * 32 + 255) / 256, 256>>>(hin, eps, l);
        k_gemm<<<dim3(MT, 2), 256>>>(zin, w1i + (size_t)l * 2 * 4096, z1p,
                                     NN, 2 * DD, DD, sc1 + l * 256, sh1 + l * 256, 1);
        if (l < 2) {
            float* hout = (l == 0) ? hA : hB;
            k_gemm<<<dim3(MT, 1), 256>>>(z1p, w2i + (size_t)l * 8192, hout,
                                         NN, DD, 2 * DD, sc2 + l * 128, sh2 + l * 128, 1);
        } else {
            k_gemm<<<dim3(MT, 1), 256>>>(z1p, w2i + (size_t)2 * 8192, (float*)d_out,
                                         NN, DD, 2 * DD, nullptr, b2 + 2 * 128, 2);
        }
    }
}

// round 16
// speedup vs baseline: 1.4437x; 1.4437x over previous
#include <cuda_runtime.h>
#include <cuda_bf16.h>
#include <math.h>

#define NN 50000
#define DD 128
#define EE 800000
#define LL 3

// ---------------- scratch (device globals: no allocation allowed) ----------------
__device__ float g_zin[NN * DD];
__device__ float g_z1[NN * 2 * DD];
__device__ float g_hA[NN * DD];
__device__ float g_hB[NN * DD];
__device__ int   g_cnt[NN];
__device__ int   g_off[NN + 1];
__device__ int   g_cursor[NN];
__device__ int   g_esrc[EE];
__device__ int   g_boff[256];
__device__ float g_sc1[LL * 256];
__device__ float g_sh1[LL * 256];
__device__ float g_sc2[2 * 128];
__device__ float g_sh2[2 * 128];
// split-bf16 weight images in the GEMM's per-thread B-load order:
// W1: per (l,ny) tile: [kt(8)][hl(2)][256 uint4]   -> 6 * 4096 uint4
// W2: per l:           [kt(16)][hl(2)][256 uint4]  -> 3 * 8192 uint4
__device__ uint4 g_w1img[6 * 4096];
__device__ uint4 g_w2img[3 * 8192];

// ---------------- helpers ----------------
__device__ __forceinline__ void split8(const float* f, uint4* h, uint4* l) {
    union { uint4 u; __nv_bfloat162 p[4]; } H, Lo;
#pragma unroll
    for (int j = 0; j < 4; j++) {
        float x0 = f[2 * j], x1 = f[2 * j + 1];
        __nv_bfloat16 h0 = __float2bfloat16(x0), h1 = __float2bfloat16(x1);
        H.p[j] = __nv_bfloat162(h0, h1);
        Lo.p[j] = __nv_bfloat162(__float2bfloat16(x0 - __bfloat162float(h0)),
                                 __float2bfloat16(x1 - __bfloat162float(h1)));
    }
    *h = H.u; *l = Lo.u;
}

// ---------------- merged setup: weight images + BN fold + cnt zero ----------------
__global__ void k_setup(const float* __restrict__ W1, const float* __restrict__ W2,
                        const float* __restrict__ b1, const float* __restrict__ g1,
                        const float* __restrict__ be1, const float* __restrict__ m1,
                        const float* __restrict__ v1, const float* __restrict__ b2,
                        const float* __restrict__ go, const float* __restrict__ bo,
                        const float* __restrict__ mo, const float* __restrict__ vo) {
    int b = blockIdx.x;
    int tid = threadIdx.x;
    if (b < 192) {
        int t = b * 256 + tid;  // 49152 total
        int half = t / 24576;
        int r = t % 24576;
        float f[8];
        uint4 h, l4;
        if (half == 0) {
            int lny = r >> 12;
            int rem = r & 4095;
            int kt = rem >> 9;
            int hl = (rem >> 8) & 1;
            int c = rem & 255;
            int krow = c >> 4, chunk = c & 15;
            int l = lny >> 1, ny = lny & 1;
            int k = kt * 16 + krow;
            int n = ny * 128 + chunk * 8;
#pragma unroll
            for (int j = 0; j < 8; j++)
                f[j] = W1[(size_t)l * 128 * 256 + (size_t)k * 256 + n + j];
            split8(f, &h, &l4);
            g_w1img[r] = hl ? l4 : h;
        } else {
            int l = r >> 13;
            int rem = r & 8191;
            int kt = rem >> 9;
            int hl = (rem >> 8) & 1;
            int c = rem & 255;
            int krow = c >> 4, chunk = c & 15;
            int k = kt * 16 + krow;
            int n = chunk * 8;
#pragma unroll
            for (int j = 0; j < 8; j++)
                f[j] = W2[(size_t)l * 256 * 128 + (size_t)k * 128 + n + j];
            split8(f, &h, &l4);
            g_w2img[r] = hl ? l4 : h;
        }
    } else if (b < 195) {
        int i = (b - 192) * 256 + tid;
        if (i < LL * 256) {
            float sc = g1[i] * rsqrtf(v1[i] + 1e-5f);
            g_sc1[i] = sc;
            g_sh1[i] = be1[i] - m1[i] * sc + b1[i] * sc;
        }
        if (i < 2 * 128) {
            float sc = go[i] * rsqrtf(vo[i] + 1e-5f);
            g_sc2[i] = sc;
            g_sh2[i] = bo[i] - mo[i] * sc + b2[i] * sc;
        }
    } else {
        int i = (b - 195) * 256 + tid;
        if (i < NN) g_cnt[i] = 0;
    }
}

// ---------------- CSR build ----------------
__global__ void k_hist(const int* __restrict__ dstp) {
    int e2 = blockIdx.x * blockDim.x + threadIdx.x;
    if (e2 * 2 < EE) {
        int2 d = *(const int2*)(dstp + e2 * 2);
        atomicAdd(&g_cnt[d.x], 1);
        atomicAdd(&g_cnt[d.y], 1);
    }
}
__global__ void k_bsum() {
    __shared__ int sh[8];
    int i = blockIdx.x * 256 + threadIdx.x;
    int lane = threadIdx.x & 31, warp = threadIdx.x >> 5;
    int v = (i < NN) ? g_cnt[i] : 0;
#pragma unroll
    for (int o = 16; o; o >>= 1) v += __shfl_xor_sync(0xffffffffu, v, o);
    if (lane == 0) sh[warp] = v;
    __syncthreads();
    if (threadIdx.x == 0) {
        int s = 0;
#pragma unroll
        for (int w = 0; w < 8; w++) s += sh[w];
        g_boff[blockIdx.x] = s;
    }
}
__global__ void k_bscan() {
    __shared__ int s[256];
    int t = threadIdx.x;
    s[t] = (t < 196) ? g_boff[t] : 0;
    __syncthreads();
    for (int off = 1; off < 256; off <<= 1) {
        int v = (t >= off) ? s[t - off] : 0;
        __syncthreads();
        s[t] += v;
        __syncthreads();
    }
    g_boff[t] = (t > 0) ? s[t - 1] : 0;
}
__global__ void k_apply() {
    __shared__ int s[256];
    int b = blockIdx.x, t = threadIdx.x;
    int i = b * 256 + t;
    int c = (i < NN) ? g_cnt[i] : 0;
    s[t] = c;
    __syncthreads();
    for (int off = 1; off < 256; off <<= 1) {
        int v = (t >= off) ? s[t - off] : 0;
        __syncthreads();
        s[t] += v;
        __syncthreads();
    }
    if (i < NN) {
        int o = g_boff[b] + s[t] - c;
        g_off[i] = o;
        g_cursor[i] = o;
    }
    if (b == 0 && t == 0) g_off[NN] = EE;
}
__global__ void k_fill(const int* __restrict__ srcp, const int* __restrict__ dstp) {
    int e2 = blockIdx.x * blockDim.x + threadIdx.x;
    if (e2 * 2 < EE) {
        int2 d = *(const int2*)(dstp + e2 * 2);
        int2 s = *(const int2*)(srcp + e2 * 2);
        int p0 = atomicAdd(&g_cursor[d.x], 1);
        g_esrc[p0] = s.x;
        int p1 = atomicAdd(&g_cursor[d.y], 1);
        g_esrc[p1] = s.y;
    }
}

// ---------------- aggregation: zin = (1+eps)*h + segment_sum(h[src] by dst) ----------------
__global__ void k_agg(const float* __restrict__ hin, const float* __restrict__ epsp, int l) {
    int warp = (blockIdx.x * blockDim.x + threadIdx.x) >> 5;
    int lane = threadIdx.x & 31;
    if (warp >= NN) return;
    int beg = g_off[warp];
    int end = g_off[warp + 1];
    float4 acc = make_float4(0.f, 0.f, 0.f, 0.f);
    for (int j = beg; j < end; j += 32) {
        int myidx = j + lane;
        int s = (myidx < end) ? g_esrc[myidx] : 0;
        int cnt = min(32, end - j);
        int t = 0;
        for (; t + 4 <= cnt; t += 4) {
            int s0 = __shfl_sync(0xffffffffu, s, t);
            int s1 = __shfl_sync(0xffffffffu, s, t + 1);
            int s2 = __shfl_sync(0xffffffffu, s, t + 2);
            int s3 = __shfl_sync(0xffffffffu, s, t + 3);
            float4 v0 = *(const float4*)(hin + (size_t)s0 * DD + lane * 4);
            float4 v1 = *(const float4*)(hin + (size_t)s1 * DD + lane * 4);
            float4 v2 = *(const float4*)(hin + (size_t)s2 * DD + lane * 4);
            float4 v3 = *(const float4*)(hin + (size_t)s3 * DD + lane * 4);
            acc.x += v0.x + v1.x + v2.x + v3.x;
            acc.y += v0.y + v1.y + v2.y + v3.y;
            acc.z += v0.z + v1.z + v2.z + v3.z;
            acc.w += v0.w + v1.w + v2.w + v3.w;
        }
        for (; t < cnt; t++) {
            int sj = __shfl_sync(0xffffffffu, s, t);
            float4 v = *(const float4*)(hin + (size_t)sj * DD + lane * 4);
            acc.x += v.x; acc.y += v.y; acc.z += v.z; acc.w += v.w;
        }
    }
    float ev = 1.0f + epsp[l];
    float4 hv = *(const float4*)(hin + (size_t)warp * DD + lane * 4);
    acc.x += ev * hv.x; acc.y += ev * hv.y; acc.z += ev * hv.z; acc.w += ev * hv.w;
    *(float4*)(g_zin + (size_t)warp * DD + lane * 4) = acc;
}

// ---------------- split-bf16 tensor-core GEMM with fused epilogue (R13 proven) ----------------
// C[M,Nn] = epilogue(A[M,K] @ B[K,Nn]) via  Ah*Bh + Ah*Bl + Al*Bh  (fp32 accum)
#define BM 128
#define BN 128
#define BK 16
#define ASTR 24
#define BSTR 136

__device__ __forceinline__ void ldsm4(unsigned r[4], const __nv_bfloat16* p) {
    unsigned addr = (unsigned)__cvta_generic_to_shared(p);
    asm volatile("ldmatrix.sync.aligned.m8n8.x4.shared.b16 {%0,%1,%2,%3}, [%4];"
                 : "=r"(r[0]), "=r"(r[1]), "=r"(r[2]), "=r"(r[3]) : "r"(addr));
}
__device__ __forceinline__ void ldsm4t(unsigned r[4], const __nv_bfloat16* p) {
    unsigned addr = (unsigned)__cvta_generic_to_shared(p);
    asm volatile("ldmatrix.sync.aligned.m8n8.x4.trans.shared.b16 {%0,%1,%2,%3}, [%4];"
                 : "=r"(r[0]), "=r"(r[1]), "=r"(r[2]), "=r"(r[3]) : "r"(addr));
}
__device__ __forceinline__ void mma16816(float c[4], const unsigned a[4], unsigned b0, unsigned b1) {
    asm volatile("mma.sync.aligned.m16n8k16.row.col.f32.bf16.bf16.f32 "
                 "{%0,%1,%2,%3},{%4,%5,%6,%7},{%8,%9},{%0,%1,%2,%3};"
                 : "+f"(c[0]), "+f"(c[1]), "+f"(c[2]), "+f"(c[3])
                 : "r"(a[0]), "r"(a[1]), "r"(a[2]), "r"(a[3]), "r"(b0), "r"(b1));
}

__global__ __launch_bounds__(256, 2) void k_gemm(
    const float* __restrict__ A, const uint4* __restrict__ Bimg, float* __restrict__ C,
    int M, int Nn, int K,
    const float* __restrict__ scale, const float* __restrict__ shift, int fuse_relu) {
    __shared__ __align__(16) __nv_bfloat16 Ah[BM * ASTR];
    __shared__ __align__(16) __nv_bfloat16 Al[BM * ASTR];
    __shared__ __align__(16) __nv_bfloat16 Bh[BK * BSTR];
    __shared__ __align__(16) __nv_bfloat16 Bl[BK * BSTR];

    int tid = threadIdx.x;
    int lane = tid & 31, warp = tid >> 5;
    int wm = (warp >> 1) * 32;
    int wn = (warp & 1) * 64;
    int m0 = blockIdx.x * BM, n0 = blockIdx.y * BN;
    Bimg += (size_t)blockIdx.y * 4096;

    float acc[2][8][4];
#pragma unroll
    for (int i = 0; i < 2; i++)
#pragma unroll
        for (int j = 0; j < 8; j++)
#pragma unroll
            for (int q = 0; q < 4; q++) acc[i][j][q] = 0.f;

    float4 ar[2];
    uint4 brh, brl;
    const int a_row0 = tid >> 2, a_c4 = tid & 3;
    const int a_row1 = (tid + 256) >> 2;
    const int b_krow = tid >> 4, b_chunk = tid & 15;

#define LDG_TILE(kt)                                                                     \
    {                                                                                    \
        int gr0 = m0 + a_row0, gr1 = m0 + a_row1;                                        \
        int k0 = (kt) * BK;                                                              \
        ar[0] = (gr0 < M) ? *(const float4*)(A + (size_t)gr0 * K + k0 + a_c4 * 4)        \
                          : make_float4(0.f, 0.f, 0.f, 0.f);                             \
        ar[1] = (gr1 < M) ? *(const float4*)(A + (size_t)gr1 * K + k0 + a_c4 * 4)        \
                          : make_float4(0.f, 0.f, 0.f, 0.f);                             \
        brh = Bimg[(kt) * 512 + tid];                                                    \
        brl = Bimg[(kt) * 512 + 256 + tid];                                              \
    }

#define STS_TILE()                                                                       \
    {                                                                                    \
        _Pragma("unroll") for (int p = 0; p < 2; p++) {                                  \
            int arow = p ? a_row1 : a_row0;                                              \
            const float* v = (const float*)&ar[p];                                       \
            _Pragma("unroll") for (int j = 0; j < 2; j++) {                              \
                __nv_bfloat16 h0 = __float2bfloat16(v[2 * j]);                           \
                __nv_bfloat16 h1 = __float2bfloat16(v[2 * j + 1]);                       \
                __nv_bfloat16 l0 = __float2bfloat16(v[2 * j] - __bfloat162float(h0));    \
                __nv_bfloat16 l1 = __float2bfloat16(v[2 * j + 1] - __bfloat162float(h1));\
                *(__nv_bfloat162*)&Ah[arow * ASTR + a_c4 * 4 + 2 * j] =                  \
                    __nv_bfloat162(h0, h1);                                              \
                *(__nv_bfloat162*)&Al[arow * ASTR + a_c4 * 4 + 2 * j] =                  \
                    __nv_bfloat162(l0, l1);                                              \
            }                                                                            \
        }                                                                                \
        *(uint4*)&Bh[b_krow * BSTR + b_chunk * 8] = brh;                                 \
        *(uint4*)&Bl[b_krow * BSTR + b_chunk * 8] = brl;                                 \
    }

    const int a_lrow = wm + (lane & 15);
    const int a_lkof = (lane >> 4) * 8;
    const int b_lk = (lane & 7) + ((lane >> 3) & 1) * 8;
    const int b_lnof = ((lane >> 4) & 1) * 8;

#define LDB(BS, bfr)                                                                     \
    {                                                                                    \
        _Pragma("unroll") for (int ntp = 0; ntp < 4; ntp++)                              \
            ldsm4t(bfr[ntp], &BS[b_lk * BSTR + wn + ntp * 16 + b_lnof]);                 \
    }
#define PASSF(AS, bfr)                                                                   \
    {                                                                                    \
        unsigned afr[2][4];                                                              \
        _Pragma("unroll") for (int mt = 0; mt < 2; mt++)                                 \
            ldsm4(afr[mt], &AS[(a_lrow + mt * 16) * ASTR + a_lkof]);                     \
        _Pragma("unroll") for (int mt = 0; mt < 2; mt++)                                 \
            _Pragma("unroll") for (int ntp = 0; ntp < 4; ntp++) {                        \
                mma16816(acc[mt][2 * ntp], afr[mt], bfr[ntp][0], bfr[ntp][1]);           \
                mma16816(acc[mt][2 * ntp + 1], afr[mt], bfr[ntp][2], bfr[ntp][3]);       \
            }                                                                            \
    }

    LDG_TILE(0);
    STS_TILE();
    __syncthreads();
    int nIter = K / BK;
    for (int t = 0; t < nIter; t++) {
        bool have = (t + 1 < nIter);
        if (have) LDG_TILE(t + 1);
        {
            unsigned bfr[4][4];
            LDB(Bh, bfr);
            PASSF(Ah, bfr);
            PASSF(Al, bfr);
            LDB(Bl, bfr);
            PASSF(Ah, bfr);
        }
        __syncthreads();
        if (have) {
            STS_TILE();
            __syncthreads();
        }
    }

    int grp = lane >> 2, tig = lane & 3;
#pragma unroll
    for (int mt = 0; mt < 2; mt++) {
#pragma unroll
        for (int nt = 0; nt < 8; nt++) {
            int col = n0 + wn + nt * 8 + tig * 2;
            float2 sc = make_float2(0.f, 0.f), sh;
            sh = *(const float2*)(shift + col);
            if (fuse_relu) sc = *(const float2*)(scale + col);
            int row0 = m0 + wm + mt * 16 + grp;
            int row1 = row0 + 8;
            float* c = acc[mt][nt];
            float2 o0, o1;
            if (fuse_relu) {
                o0.x = fmaxf(c[0] * sc.x + sh.x, 0.f);
                o0.y = fmaxf(c[1] * sc.y + sh.y, 0.f);
                o1.x = fmaxf(c[2] * sc.x + sh.x, 0.f);
                o1.y = fmaxf(c[3] * sc.y + sh.y, 0.f);
            } else {
                o0.x = c[0] + sh.x;
                o0.y = c[1] + sh.y;
                o1.x = c[2] + sh.x;
                o1.y = c[3] + sh.y;
            }
            if (row0 < M) *(float2*)(C + (size_t)row0 * Nn + col) = o0;
            if (row1 < M) *(float2*)(C + (size_t)row1 * Nn + col) = o1;
        }
    }
#undef LDG_TILE
#undef STS_TILE
#undef LDB
#undef PASSF
}

// ---------------- log_softmax over D=128, warp per row, in place (fast-math) ----------------
__global__ void k_lsm(float* __restrict__ out) {
    int warp = (blockIdx.x * blockDim.x + threadIdx.x) >> 5;
    int lane = threadIdx.x & 31;
    if (warp >= NN) return;
    float4 v = *(float4*)(out + (size_t)warp * DD + lane * 4);
    float mx = fmaxf(fmaxf(v.x, v.y), fmaxf(v.z, v.w));
#pragma unroll
    for (int o = 16; o; o >>= 1) mx = fmaxf(mx, __shfl_xor_sync(0xffffffffu, mx, o));
    float s = __expf(v.x - mx) + __expf(v.y - mx) + __expf(v.z - mx) + __expf(v.w - mx);
#pragma unroll
    for (int o = 16; o; o >>= 1) s += __shfl_xor_sync(0xffffffffu, s, o);
    float lse = mx + __logf(s);
    v.x -= lse; v.y -= lse; v.z -= lse; v.w -= lse;
    *(float4*)(out + (size_t)warp * DD + lane * 4) = v;
}

// ---------------- launch ----------------
extern "C" void kernel_launch(void* const* d_in, const int* in_sizes, int n_in,
                              void* d_out, int out_size) {
    const float* x   = (const float*)d_in[0];
    const int*   ei  = (const int*)d_in[1];
    const float* W1  = (const float*)d_in[2];
    const float* b1  = (const float*)d_in[3];
    const float* g1  = (const float*)d_in[4];
    const float* be1 = (const float*)d_in[5];
    const float* m1  = (const float*)d_in[6];
    const float* v1  = (const float*)d_in[7];
    const float* W2  = (const float*)d_in[8];
    const float* b2  = (const float*)d_in[9];
    const float* eps = (const float*)d_in[10];
    const float* go  = (const float*)d_in[11];
    const float* bo  = (const float*)d_in[12];
    const float* mo  = (const float*)d_in[13];
    const float* vo  = (const float*)d_in[14];
    const int* srcp = ei;
    const int* dstp = ei + EE;

    float *zin, *z1p, *hA, *hB, *sc1, *sh1, *sc2, *sh2;
    uint4 *w1i, *w2i;
    cudaGetSymbolAddress((void**)&zin, g_zin);
    cudaGetSymbolAddress((void**)&z1p, g_z1);
    cudaGetSymbolAddress((void**)&hA, g_hA);
    cudaGetSymbolAddress((void**)&hB, g_hB);
    cudaGetSymbolAddress((void**)&sc1, g_sc1);
    cudaGetSymbolAddress((void**)&sh1, g_sh1);
    cudaGetSymbolAddress((void**)&sc2, g_sc2);
    cudaGetSymbolAddress((void**)&sh2, g_sh2);
    cudaGetSymbolAddress((void**)&w1i, g_w1img);
    cudaGetSymbolAddress((void**)&w2i, g_w2img);

    k_setup<<<391, 256>>>(W1, W2, b1, g1, be1, m1, v1, b2, go, bo, mo, vo);
    k_hist<<<(EE / 2 + 255) / 256, 256>>>(dstp);
    const int SB = (NN + 255) / 256;  // 196
    k_bsum<<<SB, 256>>>();
    k_bscan<<<1, 256>>>();
    k_apply<<<SB, 256>>>();
    k_fill<<<(EE / 2 + 255) / 256, 256>>>(srcp, dstp);

    const int MT = (NN + BM - 1) / BM;  // 391
    for (int l = 0; l < LL; l++) {
        const float* hin = (l == 0) ? x : ((l == 1) ? hA : hB);
        k_agg<<<(NN * 32 + 255) / 256, 256>>>(hin, eps, l);
        k_gemm<<<dim3(MT, 2), 256>>>(zin, w1i + (size_t)l * 2 * 4096, z1p,
                                     NN, 2 * DD, DD, sc1 + l * 256, sh1 + l * 256, 1);
        if (l < 2) {
            float* hout = (l == 0) ? hA : hB;
            k_gemm<<<dim3(MT, 1), 256>>>(z1p, w2i + (size_t)l * 8192, hout,
                                         NN, DD, 2 * DD, sc2 + l * 128, sh2 + l * 128, 1);
        } else {
            k_gemm<<<dim3(MT, 1), 256>>>(z1p, w2i + (size_t)2 * 8192, (float*)d_out,
                                         NN, DD, 2 * DD, nullptr, b2 + 2 * 128, 0);
        }
    }
    k_lsm<<<(NN * 32 + 255) / 256, 256>>>((float*)d_out);
}

// round 17
// speedup vs baseline: 1.4471x; 1.0023x over previous
#include <cuda_runtime.h>
#include <cuda_bf16.h>
#include <math.h>

#define NN 50000
#define DD 128
#define EE 800000
#define LL 3

// ---------------- scratch (device globals: no allocation allowed) ----------------
__device__ float g_zin[NN * DD];
__device__ float g_z1[NN * 2 * DD];
__device__ float g_hA[NN * DD];
__device__ float g_hB[NN * DD];
__device__ int   g_cnt[NN];
__device__ int   g_off[NN + 1];
__device__ int   g_cursor[NN];
__device__ int   g_esrc[EE];
__device__ int   g_boff[256];
__device__ float g_sc1[LL * 256];
__device__ float g_sh1[LL * 256];
__device__ float g_sc2[2 * 128];
__device__ float g_sh2[2 * 128];
// split-bf16 weight images in the GEMM's per-thread B-load order:
// W1: per (l,ny) tile: [kt(8)][hl(2)][256 uint4]   -> 6 * 4096 uint4
// W2: per l:           [kt(16)][hl(2)][256 uint4]  -> 3 * 8192 uint4
__device__ uint4 g_w1img[6 * 4096];
__device__ uint4 g_w2img[3 * 8192];

// ---------------- helpers ----------------
__device__ __forceinline__ void split8(const float* f, uint4* h, uint4* l) {
    union { uint4 u; __nv_bfloat162 p[4]; } H, Lo;
#pragma unroll
    for (int j = 0; j < 4; j++) {
        float x0 = f[2 * j], x1 = f[2 * j + 1];
        __nv_bfloat16 h0 = __float2bfloat16(x0), h1 = __float2bfloat16(x1);
        H.p[j] = __nv_bfloat162(h0, h1);
        Lo.p[j] = __nv_bfloat162(__float2bfloat16(x0 - __bfloat162float(h0)),
                                 __float2bfloat16(x1 - __bfloat162float(h1)));
    }
    *h = H.u; *l = Lo.u;
}

// ---------------- merged setup: weight images + BN fold + cnt zero ----------------
__global__ void k_setup(const float* __restrict__ W1, const float* __restrict__ W2,
                        const float* __restrict__ b1, const float* __restrict__ g1,
                        const float* __restrict__ be1, const float* __restrict__ m1,
                        const float* __restrict__ v1, const float* __restrict__ b2,
                        const float* __restrict__ go, const float* __restrict__ bo,
                        const float* __restrict__ mo, const float* __restrict__ vo) {
    int b = blockIdx.x;
    int tid = threadIdx.x;
    if (b < 192) {
        int t = b * 256 + tid;  // 49152 total
        int half = t / 24576;
        int r = t % 24576;
        float f[8];
        uint4 h, l4;
        if (half == 0) {
            int lny = r >> 12;
            int rem = r & 4095;
            int kt = rem >> 9;
            int hl = (rem >> 8) & 1;
            int c = rem & 255;
            int krow = c >> 4, chunk = c & 15;
            int l = lny >> 1, ny = lny & 1;
            int k = kt * 16 + krow;
            int n = ny * 128 + chunk * 8;
#pragma unroll
            for (int j = 0; j < 8; j++)
                f[j] = W1[(size_t)l * 128 * 256 + (size_t)k * 256 + n + j];
            split8(f, &h, &l4);
            g_w1img[r] = hl ? l4 : h;
        } else {
            int l = r >> 13;
            int rem = r & 8191;
            int kt = rem >> 9;
            int hl = (rem >> 8) & 1;
            int c = rem & 255;
            int krow = c >> 4, chunk = c & 15;
            int k = kt * 16 + krow;
            int n = chunk * 8;
#pragma unroll
            for (int j = 0; j < 8; j++)
                f[j] = W2[(size_t)l * 256 * 128 + (size_t)k * 128 + n + j];
            split8(f, &h, &l4);
            g_w2img[r] = hl ? l4 : h;
        }
    } else if (b < 195) {
        int i = (b - 192) * 256 + tid;
        if (i < LL * 256) {
            float sc = g1[i] * rsqrtf(v1[i] + 1e-5f);
            g_sc1[i] = sc;
            g_sh1[i] = be1[i] - m1[i] * sc + b1[i] * sc;
        }
        if (i < 2 * 128) {
            float sc = go[i] * rsqrtf(vo[i] + 1e-5f);
            g_sc2[i] = sc;
            g_sh2[i] = bo[i] - mo[i] * sc + b2[i] * sc;
        }
    } else {
        int i = (b - 195) * 256 + tid;
        if (i < NN) g_cnt[i] = 0;
    }
}

// ---------------- CSR build ----------------
__global__ void k_hist(const int* __restrict__ dstp) {
    int e2 = blockIdx.x * blockDim.x + threadIdx.x;
    if (e2 * 2 < EE) {
        int2 d = *(const int2*)(dstp + e2 * 2);
        atomicAdd(&g_cnt[d.x], 1);
        atomicAdd(&g_cnt[d.y], 1);
    }
}
__global__ void k_bsum() {
    __shared__ int sh[8];
    int i = blockIdx.x * 256 + threadIdx.x;
    int lane = threadIdx.x & 31, warp = threadIdx.x >> 5;
    int v = (i < NN) ? g_cnt[i] : 0;
#pragma unroll
    for (int o = 16; o; o >>= 1) v += __shfl_xor_sync(0xffffffffu, v, o);
    if (lane == 0) sh[warp] = v;
    __syncthreads();
    if (threadIdx.x == 0) {
        int s = 0;
#pragma unroll
        for (int w = 0; w < 8; w++) s += sh[w];
        g_boff[blockIdx.x] = s;
    }
}
__global__ void k_bscan() {
    __shared__ int s[256];
    int t = threadIdx.x;
    s[t] = (t < 196) ? g_boff[t] : 0;
    __syncthreads();
    for (int off = 1; off < 256; off <<= 1) {
        int v = (t >= off) ? s[t - off] : 0;
        __syncthreads();
        s[t] += v;
        __syncthreads();
    }
    g_boff[t] = (t > 0) ? s[t - 1] : 0;
}
__global__ void k_apply() {
    __shared__ int s[256];
    int b = blockIdx.x, t = threadIdx.x;
    int i = b * 256 + t;
    int c = (i < NN) ? g_cnt[i] : 0;
    s[t] = c;
    __syncthreads();
    for (int off = 1; off < 256; off <<= 1) {
        int v = (t >= off) ? s[t - off] : 0;
        __syncthreads();
        s[t] += v;
        __syncthreads();
    }
    if (i < NN) {
        int o = g_boff[b] + s[t] - c;
        g_off[i] = o;
        g_cursor[i] = o;
    }
    if (b == 0 && t == 0) g_off[NN] = EE;
}
__global__ void k_fill(const int* __restrict__ srcp, const int* __restrict__ dstp) {
    int e2 = blockIdx.x * blockDim.x + threadIdx.x;
    if (e2 * 2 < EE) {
        int2 d = *(const int2*)(dstp + e2 * 2);
        int2 s = *(const int2*)(srcp + e2 * 2);
        int p0 = atomicAdd(&g_cursor[d.x], 1);
        g_esrc[p0] = s.x;
        int p1 = atomicAdd(&g_cursor[d.y], 1);
        g_esrc[p1] = s.y;
    }
}

// ---------------- aggregation: zin = (1+eps)*h + segment_sum(h[src] by dst) ----------------
__global__ void k_agg(const float* __restrict__ hin, const float* __restrict__ epsp, int l) {
    int warp = (blockIdx.x * blockDim.x + threadIdx.x) >> 5;
    int lane = threadIdx.x & 31;
    if (warp >= NN) return;
    int beg = g_off[warp];
    int end = g_off[warp + 1];
    float4 acc = make_float4(0.f, 0.f, 0.f, 0.f);
    for (int j = beg; j < end; j += 32) {
        int myidx = j + lane;
        int s = (myidx < end) ? g_esrc[myidx] : 0;
        int cnt = min(32, end - j);
        int t = 0;
        for (; t + 4 <= cnt; t += 4) {
            int s0 = __shfl_sync(0xffffffffu, s, t);
            int s1 = __shfl_sync(0xffffffffu, s, t + 1);
            int s2 = __shfl_sync(0xffffffffu, s, t + 2);
            int s3 = __shfl_sync(0xffffffffu, s, t + 3);
            float4 v0 = *(const float4*)(hin + (size_t)s0 * DD + lane * 4);
            float4 v1 = *(const float4*)(hin + (size_t)s1 * DD + lane * 4);
            float4 v2 = *(const float4*)(hin + (size_t)s2 * DD + lane * 4);
            float4 v3 = *(const float4*)(hin + (size_t)s3 * DD + lane * 4);
            acc.x += v0.x + v1.x + v2.x + v3.x;
            acc.y += v0.y + v1.y + v2.y + v3.y;
            acc.z += v0.z + v1.z + v2.z + v3.z;
            acc.w += v0.w + v1.w + v2.w + v3.w;
        }
        for (; t < cnt; t++) {
            int sj = __shfl_sync(0xffffffffu, s, t);
            float4 v = *(const float4*)(hin + (size_t)sj * DD + lane * 4);
            acc.x += v.x; acc.y += v.y; acc.z += v.z; acc.w += v.w;
        }
    }
    float ev = 1.0f + epsp[l];
    float4 hv = *(const float4*)(hin + (size_t)warp * DD + lane * 4);
    acc.x += ev * hv.x; acc.y += ev * hv.y; acc.z += ev * hv.z; acc.w += ev * hv.w;
    *(float4*)(g_zin + (size_t)warp * DD + lane * 4) = acc;
}

// ---------------- split-bf16 tensor-core GEMM, templated epilogue ----------------
// OM=1: relu(acc*scale+shift) ; OM=2: acc+shift then log_softmax over full row (BN==Nn)
#define BM 128
#define BN 128
#define BK 16
#define ASTR 24
#define BSTR 136

__device__ __forceinline__ void ldsm4(unsigned r[4], const __nv_bfloat16* p) {
    unsigned addr = (unsigned)__cvta_generic_to_shared(p);
    asm volatile("ldmatrix.sync.aligned.m8n8.x4.shared.b16 {%0,%1,%2,%3}, [%4];"
                 : "=r"(r[0]), "=r"(r[1]), "=r"(r[2]), "=r"(r[3]) : "r"(addr));
}
__device__ __forceinline__ void ldsm4t(unsigned r[4], const __nv_bfloat16* p) {
    unsigned addr = (unsigned)__cvta_generic_to_shared(p);
    asm volatile("ldmatrix.sync.aligned.m8n8.x4.trans.shared.b16 {%0,%1,%2,%3}, [%4];"
                 : "=r"(r[0]), "=r"(r[1]), "=r"(r[2]), "=r"(r[3]) : "r"(addr));
}
__device__ __forceinline__ void mma16816(float c[4], const unsigned a[4], unsigned b0, unsigned b1) {
    asm volatile("mma.sync.aligned.m16n8k16.row.col.f32.bf16.bf16.f32 "
                 "{%0,%1,%2,%3},{%4,%5,%6,%7},{%8,%9},{%0,%1,%2,%3};"
                 : "+f"(c[0]), "+f"(c[1]), "+f"(c[2]), "+f"(c[3])
                 : "r"(a[0]), "r"(a[1]), "r"(a[2]), "r"(a[3]), "r"(b0), "r"(b1));
}

template <int OM>
__global__ __launch_bounds__(256, 2) void k_gemm(
    const float* __restrict__ A, const uint4* __restrict__ Bimg, float* __restrict__ C,
    int M, int Nn, int K,
    const float* __restrict__ scale, const float* __restrict__ shift) {
    __shared__ __align__(16) __nv_bfloat16 Ah[BM * ASTR];
    __shared__ __align__(16) __nv_bfloat16 Al[BM * ASTR];
    __shared__ __align__(16) __nv_bfloat16 Bh[BK * BSTR];
    __shared__ __align__(16) __nv_bfloat16 Bl[BK * BSTR];
    __shared__ float rred[BM][2];

    int tid = threadIdx.x;
    int lane = tid & 31, warp = tid >> 5;
    int wm = (warp >> 1) * 32;
    int wn = (warp & 1) * 64;
    int m0 = blockIdx.x * BM, n0 = blockIdx.y * BN;
    Bimg += (size_t)blockIdx.y * 4096;

    float acc[2][8][4];
#pragma unroll
    for (int i = 0; i < 2; i++)
#pragma unroll
        for (int j = 0; j < 8; j++)
#pragma unroll
            for (int q = 0; q < 4; q++) acc[i][j][q] = 0.f;

    float4 ar[2];
    uint4 brh, brl;
    const int a_row0 = tid >> 2, a_c4 = tid & 3;
    const int a_row1 = (tid + 256) >> 2;
    const int b_krow = tid >> 4, b_chunk = tid & 15;

#define LDG_TILE(kt)                                                                     \
    {                                                                                    \
        int gr0 = m0 + a_row0, gr1 = m0 + a_row1;                                        \
        int k0 = (kt) * BK;                                                              \
        ar[0] = (gr0 < M) ? *(const float4*)(A + (size_t)gr0 * K + k0 + a_c4 * 4)        \
                          : make_float4(0.f, 0.f, 0.f, 0.f);                             \
        ar[1] = (gr1 < M) ? *(const float4*)(A + (size_t)gr1 * K + k0 + a_c4 * 4)        \
                          : make_float4(0.f, 0.f, 0.f, 0.f);                             \
        brh = Bimg[(kt) * 512 + tid];                                                    \
        brl = Bimg[(kt) * 512 + 256 + tid];                                              \
    }

#define STS_TILE()                                                                       \
    {                                                                                    \
        _Pragma("unroll") for (int p = 0; p < 2; p++) {                                  \
            int arow = p ? a_row1 : a_row0;                                              \
            const float* v = (const float*)&ar[p];                                       \
            _Pragma("unroll") for (int j = 0; j < 2; j++) {                              \
                __nv_bfloat16 h0 = __float2bfloat16(v[2 * j]);                           \
                __nv_bfloat16 h1 = __float2bfloat16(v[2 * j + 1]);                       \
                __nv_bfloat16 l0 = __float2bfloat16(v[2 * j] - __bfloat162float(h0));    \
                __nv_bfloat16 l1 = __float2bfloat16(v[2 * j + 1] - __bfloat162float(h1));\
                *(__nv_bfloat162*)&Ah[arow * ASTR + a_c4 * 4 + 2 * j] =                  \
                    __nv_bfloat162(h0, h1);                                              \
                *(__nv_bfloat162*)&Al[arow * ASTR + a_c4 * 4 + 2 * j] =                  \
                    __nv_bfloat162(l0, l1);                                              \
            }                                                                            \
        }                                                                                \
        *(uint4*)&Bh[b_krow * BSTR + b_chunk * 8] = brh;                                 \
        *(uint4*)&Bl[b_krow * BSTR + b_chunk * 8] = brl;                                 \
    }

    const int a_lrow = wm + (lane & 15);
    const int a_lkof = (lane >> 4) * 8;
    const int b_lk = (lane & 7) + ((lane >> 3) & 1) * 8;
    const int b_lnof = ((lane >> 4) & 1) * 8;

#define LDB(BS, bfr)                                                                     \
    {                                                                                    \
        _Pragma("unroll") for (int ntp = 0; ntp < 4; ntp++)                              \
            ldsm4t(bfr[ntp], &BS[b_lk * BSTR + wn + ntp * 16 + b_lnof]);                 \
    }
#define PASSF(AS, bfr)                                                                   \
    {                                                                                    \
        unsigned afr[2][4];                                                              \
        _Pragma("unroll") for (int mt = 0; mt < 2; mt++)                                 \
            ldsm4(afr[mt], &AS[(a_lrow + mt * 16) * ASTR + a_lkof]);                     \
        _Pragma("unroll") for (int mt = 0; mt < 2; mt++)                                 \
            _Pragma("unroll") for (int ntp = 0; ntp < 4; ntp++) {                        \
                mma16816(acc[mt][2 * ntp], afr[mt], bfr[ntp][0], bfr[ntp][1]);           \
                mma16816(acc[mt][2 * ntp + 1], afr[mt], bfr[ntp][2], bfr[ntp][3]);       \
            }                                                                            \
    }

    LDG_TILE(0);
    STS_TILE();
    __syncthreads();
    int nIter = K / BK;
    for (int t = 0; t < nIter; t++) {
        bool have = (t + 1 < nIter);
        if (have) LDG_TILE(t + 1);
        {
            unsigned bfr[4][4];
            LDB(Bh, bfr);
            PASSF(Ah, bfr);
            PASSF(Al, bfr);
            LDB(Bl, bfr);
            PASSF(Ah, bfr);
        }
        __syncthreads();
        if (have) {
            STS_TILE();
            __syncthreads();
        }
    }

    int grp = lane >> 2, tig = lane & 3;
    if (OM == 1) {
#pragma unroll
        for (int mt = 0; mt < 2; mt++) {
#pragma unroll
            for (int nt = 0; nt < 8; nt++) {
                int col = n0 + wn + nt * 8 + tig * 2;
                float2 sc = *(const float2*)(scale + col);
                float2 sh = *(const float2*)(shift + col);
                int row0 = m0 + wm + mt * 16 + grp;
                int row1 = row0 + 8;
                float* c = acc[mt][nt];
                float2 o0, o1;
                o0.x = fmaxf(c[0] * sc.x + sh.x, 0.f);
                o0.y = fmaxf(c[1] * sc.y + sh.y, 0.f);
                o1.x = fmaxf(c[2] * sc.x + sh.x, 0.f);
                o1.y = fmaxf(c[3] * sc.y + sh.y, 0.f);
                if (row0 < M) *(float2*)(C + (size_t)row0 * Nn + col) = o0;
                if (row1 < M) *(float2*)(C + (size_t)row1 * Nn + col) = o1;
            }
        }
    } else {
        // OM==2: in-place acc += shift, then log_softmax over full row (BN == Nn, gridDim.y == 1)
#pragma unroll
        for (int mt = 0; mt < 2; mt++)
#pragma unroll
            for (int nt = 0; nt < 8; nt++) {
                int col = wn + nt * 8 + tig * 2;
                float2 sh = *(const float2*)(shift + col);
                acc[mt][nt][0] += sh.x;
                acc[mt][nt][1] += sh.y;
                acc[mt][nt][2] += sh.x;
                acc[mt][nt][3] += sh.y;
            }
        float rmax[2][2];
        // phase A: row max
#pragma unroll
        for (int mt = 0; mt < 2; mt++)
#pragma unroll
            for (int rh = 0; rh < 2; rh++) {
                float mx = acc[mt][0][rh * 2];
#pragma unroll
                for (int nt = 0; nt < 8; nt++)
                    mx = fmaxf(mx, fmaxf(acc[mt][nt][rh * 2], acc[mt][nt][rh * 2 + 1]));
                mx = fmaxf(mx, __shfl_xor_sync(0xffffffffu, mx, 1));
                mx = fmaxf(mx, __shfl_xor_sync(0xffffffffu, mx, 2));
                if (tig == 0) rred[wm + mt * 16 + rh * 8 + grp][warp & 1] = mx;
            }
        __syncthreads();
#pragma unroll
        for (int mt = 0; mt < 2; mt++)
#pragma unroll
            for (int rh = 0; rh < 2; rh++) {
                int rl = wm + mt * 16 + rh * 8 + grp;
                rmax[mt][rh] = fmaxf(rred[rl][0], rred[rl][1]);
            }
        __syncthreads();
        // phase B: row exp-sum
#pragma unroll
        for (int mt = 0; mt < 2; mt++)
#pragma unroll
            for (int rh = 0; rh < 2; rh++) {
                float s = 0.f;
#pragma unroll
                for (int nt = 0; nt < 8; nt++)
                    s += __expf(acc[mt][nt][rh * 2] - rmax[mt][rh]) +
                         __expf(acc[mt][nt][rh * 2 + 1] - rmax[mt][rh]);
                s += __shfl_xor_sync(0xffffffffu, s, 1);
                s += __shfl_xor_sync(0xffffffffu, s, 2);
                if (tig == 0) rred[wm + mt * 16 + rh * 8 + grp][warp & 1] = s;
            }
        __syncthreads();
        // phase C: write normalized
#pragma unroll
        for (int mt = 0; mt < 2; mt++)
#pragma unroll
            for (int rh = 0; rh < 2; rh++) {
                int rl = wm + mt * 16 + rh * 8 + grp;
                int row = m0 + rl;
                if (row >= M) continue;
                float lse = rmax[mt][rh] + __logf(rred[rl][0] + rred[rl][1]);
#pragma unroll
                for (int nt = 0; nt < 8; nt++) {
                    int col = wn + nt * 8 + tig * 2;
                    float2 o;
                    o.x = acc[mt][nt][rh * 2] - lse;
                    o.y = acc[mt][nt][rh * 2 + 1] - lse;
                    *(float2*)(C + (size_t)row * Nn + col) = o;
                }
            }
    }
#undef LDG_TILE
#undef STS_TILE
#undef LDB
#undef PASSF
}

// ---------------- launch ----------------
extern "C" void kernel_launch(void* const* d_in, const int* in_sizes, int n_in,
                              void* d_out, int out_size) {
    const float* x   = (const float*)d_in[0];
    const int*   ei  = (const int*)d_in[1];
    const float* W1  = (const float*)d_in[2];
    const float* b1  = (const float*)d_in[3];
    const float* g1  = (const float*)d_in[4];
    const float* be1 = (const float*)d_in[5];
    const float* m1  = (const float*)d_in[6];
    const float* v1  = (const float*)d_in[7];
    const float* W2  = (const float*)d_in[8];
    const float* b2  = (const float*)d_in[9];
    const float* eps = (const float*)d_in[10];
    const float* go  = (const float*)d_in[11];
    const float* bo  = (const float*)d_in[12];
    const float* mo  = (const float*)d_in[13];
    const float* vo  = (const float*)d_in[14];
    const int* srcp = ei;
    const int* dstp = ei + EE;

    float *zin, *z1p, *hA, *hB, *sc1, *sh1, *sc2, *sh2;
    uint4 *w1i, *w2i;
    cudaGetSymbolAddress((void**)&zin, g_zin);
    cudaGetSymbolAddress((void**)&z1p, g_z1);
    cudaGetSymbolAddress((void**)&hA, g_hA);
    cudaGetSymbolAddress((void**)&hB, g_hB);
    cudaGetSymbolAddress((void**)&sc1, g_sc1);
    cudaGetSymbolAddress((void**)&sh1, g_sh1);
    cudaGetSymbolAddress((void**)&sc2, g_sc2);
    cudaGetSymbolAddress((void**)&sh2, g_sh2);
    cudaGetSymbolAddress((void**)&w1i, g_w1img);
    cudaGetSymbolAddress((void**)&w2i, g_w2img);

    k_setup<<<391, 256>>>(W1, W2, b1, g1, be1, m1, v1, b2, go, bo, mo, vo);
    k_hist<<<(EE / 2 + 255) / 256, 256>>>(dstp);
    const int SB = (NN + 255) / 256;  // 196
    k_bsum<<<SB, 256>>>();
    k_bscan<<<1, 256>>>();
    k_apply<<<SB, 256>>>();
    k_fill<<<(EE / 2 + 255) / 256, 256>>>(srcp, dstp);

    const int MT = (NN + BM - 1) / BM;  // 391
    for (int l = 0; l < LL; l++) {
        const float* hin = (l == 0) ? x : ((l == 1) ? hA : hB);
        k_agg<<<(NN * 32 + 255) / 256, 256>>>(hin, eps, l);
        k_gemm<1><<<dim3(MT, 2), 256>>>(zin, w1i + (size_t)l * 2 * 4096, z1p,
                                        NN, 2 * DD, DD, sc1 + l * 256, sh1 + l * 256);
        if (l < 2) {
            float* hout = (l == 0) ? hA : hB;
            k_gemm<1><<<dim3(MT, 1), 256>>>(z1p, w2i + (size_t)l * 8192, hout,
                                            NN, DD, 2 * DD, sc2 + l * 128, sh2 + l * 128);
        } else {
            k_gemm<2><<<dim3(MT, 1), 256>>>(z1p, w2i + (size_t)2 * 8192, (float*)d_out,
                                            NN, DD, 2 * DD, nullptr, b2 + 2 * 128);
        }
    }
}